// round 2
// baseline (speedup 1.0000x reference)
#include <cuda_runtime.h>
#include <math.h>

// ---------------- problem constants ----------------
constexpr int Bb = 32, HW = 784, C = 384, T = 785, TP = 197, FF = 1536;
constexpr int NH = 8, HD = 48;
constexpr int CUT = 588, NPOOL = 196;
constexpr float EPS = 1e-5f;

constexpr int BTC = Bb * T * C;     // 9,646,080
constexpr int X2N = Bb * TP * C;    // 2,420,736
constexpr int H1N = Bb * TP * FF;   // 9,682,944

// ---------------- scratch (device globals; no allocation) ----------------
__device__ float d_xin[BTC];
__device__ float d_x1[BTC];
__device__ float d_q[BTC];
__device__ float d_k[BTC];
__device__ float d_v[BTC];
__device__ float d_ao[BTC];
__device__ float d_mhsa[BTC];
__device__ float d_res1[BTC];
__device__ float d_ci[Bb * C];
__device__ float d_ca[Bb * HW];
__device__ int   d_sel[Bb * NPOOL];
__device__ float d_x2[X2N];
__device__ float d_x2n[X2N];
__device__ float d_h1[H1N];

// ---------------- concat cls + x -> x_in ----------------
__global__ void concat_kernel(const float* __restrict__ x, const float* __restrict__ cls) {
    int idx = blockIdx.x * blockDim.x + threadIdx.x;
    if (idx >= BTC) return;
    int b = idx / (T * C);
    int rem = idx - b * (T * C);
    int t = rem / C;
    int c = rem - t * C;
    float v;
    if (t == 0) v = cls[b * C + c];
    else        v = x[((size_t)b * HW + (t - 1)) * C + c];
    d_xin[idx] = v;
}

// ---------------- LayerNorm over (rows, C) per batch ----------------
__global__ void ln_kernel(const float* __restrict__ x, const float* __restrict__ w,
                          const float* __restrict__ bia, float* __restrict__ y, int rows) {
    int b = blockIdx.x;
    const float* xb = x + (size_t)b * rows * C;
    float* yb = y + (size_t)b * rows * C;
    int n = rows * C;
    float s = 0.f, s2 = 0.f;
    for (int i = threadIdx.x; i < n; i += blockDim.x) {
        float v = xb[i];
        s += v;
        s2 = fmaf(v, v, s2);
    }
    __shared__ float red1[32], red2[32];
    int lane = threadIdx.x & 31, wid = threadIdx.x >> 5;
    #pragma unroll
    for (int o = 16; o > 0; o >>= 1) {
        s  += __shfl_down_sync(0xffffffffu, s, o);
        s2 += __shfl_down_sync(0xffffffffu, s2, o);
    }
    if (lane == 0) { red1[wid] = s; red2[wid] = s2; }
    __syncthreads();
    __shared__ float mu_s, rs_s;
    if (threadIdx.x == 0) {
        float ts = 0.f, ts2 = 0.f;
        int nw = blockDim.x >> 5;
        for (int i = 0; i < nw; i++) { ts += red1[i]; ts2 += red2[i]; }
        float mu = ts / (float)n;
        float var = ts2 / (float)n - mu * mu;
        mu_s = mu;
        rs_s = rsqrtf(var + EPS);
    }
    __syncthreads();
    float mu = mu_s, rs = rs_s;
    for (int i = threadIdx.x; i < n; i += blockDim.x)
        yb[i] = (xb[i] - mu) * rs * w[i] + bia[i];
}

// ---------------- tiled NT GEMM: Co[m,n] = sum_k A[m,k] * W[n,k] ----------------
// EPI 0: plain   1: exact GELU   2: Co=v, aux2=aux+v (Wo+residual)
// EPI 3: v2=aux+v, scatter to final output (nodes/cls split); Co unused
template <int EPI>
__global__ void gemm_nt(const float* __restrict__ A, const float* __restrict__ W,
                        float* __restrict__ Co, int M, int N, int K,
                        const float* __restrict__ aux, float* __restrict__ aux2) {
    constexpr int BM = 64, BN = 64, BK = 32;
    __shared__ float As[BK][BM + 4];
    __shared__ float Ws[BK][BN + 4];
    int tid = threadIdx.x;
    int tm = tid >> 4, tn = tid & 15;
    int m0 = blockIdx.y * BM, n0 = blockIdx.x * BN;
    float acc[4][4];
    #pragma unroll
    for (int i = 0; i < 4; i++)
        #pragma unroll
        for (int j = 0; j < 4; j++) acc[i][j] = 0.f;

    for (int k0 = 0; k0 < K; k0 += BK) {
        for (int i = tid; i < BM * BK; i += 256) {
            int r = i >> 5, c = i & 31;
            int gm = m0 + r;
            As[c][r] = (gm < M) ? A[(size_t)gm * K + k0 + c] : 0.f;
        }
        for (int i = tid; i < BN * BK; i += 256) {
            int r = i >> 5, c = i & 31;
            int gn = n0 + r;
            Ws[c][r] = (gn < N) ? W[(size_t)gn * K + k0 + c] : 0.f;
        }
        __syncthreads();
        #pragma unroll
        for (int kk = 0; kk < BK; kk++) {
            float4 a4 = *reinterpret_cast<const float4*>(&As[kk][tm * 4]);
            float4 b4 = *reinterpret_cast<const float4*>(&Ws[kk][tn * 4]);
            float a[4] = {a4.x, a4.y, a4.z, a4.w};
            float bb[4] = {b4.x, b4.y, b4.z, b4.w};
            #pragma unroll
            for (int i = 0; i < 4; i++)
                #pragma unroll
                for (int j = 0; j < 4; j++)
                    acc[i][j] = fmaf(a[i], bb[j], acc[i][j]);
        }
        __syncthreads();
    }

    #pragma unroll
    for (int i = 0; i < 4; i++) {
        int gm = m0 + tm * 4 + i;
        if (gm >= M) continue;
        #pragma unroll
        for (int j = 0; j < 4; j++) {
            int gn = n0 + tn * 4 + j;
            if (gn >= N) continue;
            float v = acc[i][j];
            size_t idx = (size_t)gm * N + gn;
            if (EPI == 0) {
                Co[idx] = v;
            } else if (EPI == 1) {
                Co[idx] = 0.5f * v * (1.f + erff(v * 0.70710678118654752f));
            } else if (EPI == 2) {
                Co[idx] = v;
                aux2[idx] = aux[idx] + v;
            } else {
                float v2 = aux[idx] + v;
                int b = gm / TP;
                int t = gm - b * TP;
                if (t == 0)
                    aux2[(size_t)Bb * NPOOL * C + (size_t)b * C + gn] = v2;
                else
                    aux2[((size_t)b * NPOOL + (t - 1)) * C + gn] = v2;
            }
        }
    }
}

// ---------------- flash attention: one thread per query row ----------------
__global__ void attn_kernel() {
    int qt = blockIdx.x, h = blockIdx.y, b = blockIdx.z;
    int r = threadIdx.x;  // 0..63
    __shared__ float4 Ks[64 * 12];
    __shared__ float4 Vs[64 * 12];
    int qrow = qt * 64 + r;
    bool valid = qrow < T;
    float4 qv[12], accv[12];
    {
        const float4* qp = reinterpret_cast<const float4*>(
            d_q + ((size_t)(b * T + (valid ? qrow : 0))) * C + h * HD);
        #pragma unroll
        for (int i = 0; i < 12; i++) {
            qv[i] = valid ? qp[i] : make_float4(0.f, 0.f, 0.f, 0.f);
            accv[i] = make_float4(0.f, 0.f, 0.f, 0.f);
        }
    }
    float m = -INFINITY, l = 0.f;
    const float scale = 0.14433756729740643f;  // 1/sqrt(48)

    for (int kt = 0; kt < (T + 63) / 64; kt++) {
        int kbase = kt * 64;
        for (int i = r; i < 64 * 12; i += 64) {
            int kr = i / 12, kc = i - kr * 12;
            int gk = kbase + kr;
            if (gk < T) {
                const float4* kp = reinterpret_cast<const float4*>(
                    d_k + ((size_t)(b * T + gk)) * C + h * HD);
                const float4* vp = reinterpret_cast<const float4*>(
                    d_v + ((size_t)(b * T + gk)) * C + h * HD);
                Ks[i] = kp[kc];
                Vs[i] = vp[kc];
            } else {
                Ks[i] = make_float4(0.f, 0.f, 0.f, 0.f);
                Vs[i] = make_float4(0.f, 0.f, 0.f, 0.f);
            }
        }
        __syncthreads();
        int nk = min(64, T - kbase);
        if (valid) {
            for (int j0 = 0; j0 < nk; j0 += 16) {
                int cnt = min(16, nk - j0);
                float s[16];
                float mloc = -INFINITY;
                #pragma unroll
                for (int jj = 0; jj < 16; jj++) {
                    if (jj < cnt) {
                        float dot = 0.f;
                        const float4* kr4 = &Ks[(j0 + jj) * 12];
                        #pragma unroll
                        for (int c = 0; c < 12; c++) {
                            float4 kv = kr4[c];
                            dot = fmaf(qv[c].x, kv.x, dot);
                            dot = fmaf(qv[c].y, kv.y, dot);
                            dot = fmaf(qv[c].z, kv.z, dot);
                            dot = fmaf(qv[c].w, kv.w, dot);
                        }
                        s[jj] = dot * scale;
                        mloc = fmaxf(mloc, s[jj]);
                    }
                }
                float mnew = fmaxf(m, mloc);
                float alpha = __expf(m - mnew);
                l *= alpha;
                #pragma unroll
                for (int c = 0; c < 12; c++) {
                    accv[c].x *= alpha; accv[c].y *= alpha;
                    accv[c].z *= alpha; accv[c].w *= alpha;
                }
                #pragma unroll
                for (int jj = 0; jj < 16; jj++) {
                    if (jj < cnt) {
                        float p = __expf(s[jj] - mnew);
                        l += p;
                        const float4* vr4 = &Vs[(j0 + jj) * 12];
                        #pragma unroll
                        for (int c = 0; c < 12; c++) {
                            float4 vv = vr4[c];
                            accv[c].x = fmaf(p, vv.x, accv[c].x);
                            accv[c].y = fmaf(p, vv.y, accv[c].y);
                            accv[c].z = fmaf(p, vv.z, accv[c].z);
                            accv[c].w = fmaf(p, vv.w, accv[c].w);
                        }
                    }
                }
                m = mnew;
            }
        }
        __syncthreads();
    }
    if (valid) {
        float inv = 1.f / l;
        float4* op = reinterpret_cast<float4*>(d_ao + ((size_t)(b * T + qrow)) * C + h * HD);
        #pragma unroll
        for (int c = 0; c < 12; c++) {
            float4 o;
            o.x = accv[c].x * inv; o.y = accv[c].y * inv;
            o.z = accv[c].z * inv; o.w = accv[c].w * inv;
            op[c] = o;
        }
    }
}

// ---------------- ci = sigmoid(mean_t mhsa) ----------------
__global__ void ci_kernel() {
    int b = blockIdx.x;
    int c = threadIdx.x;  // 384 threads
    float s = 0.f;
    for (int t = 0; t < T; t++) s += d_mhsa[((size_t)b * T + t) * C + c];
    float mu = s / (float)T;
    d_ci[b * C + c] = 1.f / (1.f + expf(-mu));
}

// ---------------- ca[b,n] = dot(nodes[b,n], ci[b]) ----------------
__global__ void ca_kernel() {
    int row = blockIdx.x * 8 + (threadIdx.x >> 5);
    int lane = threadIdx.x & 31;
    if (row >= Bb * HW) return;
    int b = row / HW, n = row - b * HW;
    const float* p = d_res1 + ((size_t)b * T + 1 + n) * C;
    const float* cc = d_ci + b * C;
    float s = 0.f;
    for (int i = lane; i < C; i += 32) s = fmaf(p[i], cc[i], s);
    #pragma unroll
    for (int o = 16; o > 0; o >>= 1) s += __shfl_down_sync(0xffffffffu, s, o);
    if (lane == 0) d_ca[row] = s;
}

// ---------------- stable ascending rank; keep top quarter in sorted order ----------------
__global__ void rank_kernel() {
    int b = blockIdx.x;
    __shared__ float s[HW];
    for (int i = threadIdx.x; i < HW; i += blockDim.x) s[i] = d_ca[b * HW + i];
    __syncthreads();
    for (int n = threadIdx.x; n < HW; n += blockDim.x) {
        float v = s[n];
        int r = 0;
        for (int mm = 0; mm < HW; mm++) {
            float u = s[mm];
            r += (u < v) || (u == v && mm < n);
        }
        if (r >= CUT) d_sel[b * NPOOL + (r - CUT)] = n;
    }
}

// ---------------- gather x2 = [cls_row, pooled nodes] ----------------
__global__ void gather_kernel() {
    int idx = blockIdx.x * blockDim.x + threadIdx.x;
    if (idx >= X2N) return;
    int b = idx / (TP * C);
    int rem = idx - b * (TP * C);
    int t = rem / C;
    int c = rem - t * C;
    int srcrow = (t == 0) ? 0 : (1 + d_sel[b * NPOOL + t - 1]);
    d_x2[idx] = d_res1[((size_t)b * T + srcrow) * C + c];
}

// ---------------- launch ----------------
extern "C" void kernel_launch(void* const* d_in, const int* in_sizes, int n_in,
                              void* d_out, int out_size) {
    const float* x    = (const float*)d_in[0];
    const float* cls  = (const float*)d_in[1];
    const float* wln1 = (const float*)d_in[2];
    const float* bln1 = (const float*)d_in[3];
    const float* Wq   = (const float*)d_in[4];
    const float* Wk   = (const float*)d_in[5];
    const float* Wv   = (const float*)d_in[6];
    const float* Wo   = (const float*)d_in[7];
    const float* wln2 = (const float*)d_in[8];
    const float* bln2 = (const float*)d_in[9];
    const float* W1   = (const float*)d_in[10];
    const float* W2   = (const float*)d_in[11];
    float* out = (float*)d_out;

    float *p_xin, *p_x1, *p_q, *p_k, *p_v, *p_ao, *p_mhsa, *p_res1, *p_x2, *p_x2n, *p_h1;
    cudaGetSymbolAddress((void**)&p_xin,  d_xin);
    cudaGetSymbolAddress((void**)&p_x1,   d_x1);
    cudaGetSymbolAddress((void**)&p_q,    d_q);
    cudaGetSymbolAddress((void**)&p_k,    d_k);
    cudaGetSymbolAddress((void**)&p_v,    d_v);
    cudaGetSymbolAddress((void**)&p_ao,   d_ao);
    cudaGetSymbolAddress((void**)&p_mhsa, d_mhsa);
    cudaGetSymbolAddress((void**)&p_res1, d_res1);
    cudaGetSymbolAddress((void**)&p_x2,   d_x2);
    cudaGetSymbolAddress((void**)&p_x2n,  d_x2n);
    cudaGetSymbolAddress((void**)&p_h1,   d_h1);

    concat_kernel<<<(BTC + 255) / 256, 256>>>(x, cls);
    ln_kernel<<<Bb, 1024>>>(p_xin, wln1, bln1, p_x1, T);

    dim3 gqkv(C / 64, (Bb * T + 63) / 64);
    gemm_nt<0><<<gqkv, 256>>>(p_x1, Wq, p_q, Bb * T, C, C, nullptr, nullptr);
    gemm_nt<0><<<gqkv, 256>>>(p_x1, Wk, p_k, Bb * T, C, C, nullptr, nullptr);
    gemm_nt<0><<<gqkv, 256>>>(p_x1, Wv, p_v, Bb * T, C, C, nullptr, nullptr);

    attn_kernel<<<dim3((T + 63) / 64, NH, Bb), 64>>>();

    gemm_nt<2><<<gqkv, 256>>>(p_ao, Wo, p_mhsa, Bb * T, C, C, p_xin, p_res1);

    ci_kernel<<<Bb, C>>>();
    ca_kernel<<<(Bb * HW + 7) / 8, 256>>>();
    rank_kernel<<<Bb, 256>>>();
    gather_kernel<<<(X2N + 255) / 256, 256>>>();

    ln_kernel<<<Bb, 1024>>>(p_x2, wln2, bln2, p_x2n, TP);

    gemm_nt<1><<<dim3(FF / 64, (Bb * TP + 63) / 64), 256>>>(
        p_x2n, W1, p_h1, Bb * TP, FF, C, nullptr, nullptr);
    gemm_nt<3><<<dim3(C / 64, (Bb * TP + 63) / 64), 256>>>(
        p_h1, W2, nullptr, Bb * TP, C, FF, p_x2n, out);
}

// round 3
// speedup vs baseline: 1.3022x; 1.3022x over previous
#include <cuda_runtime.h>
#include <math.h>

// ---------------- problem constants ----------------
constexpr int Bb = 32, HW = 784, C = 384, T = 785, TP = 197, FF = 1536;
constexpr int NH = 8, HD = 48;
constexpr int CUT = 588, NPOOL = 196;
constexpr float EPS = 1e-5f;

constexpr int BTC = Bb * T * C;
constexpr int X2N = Bb * TP * C;
constexpr int H1N = Bb * TP * FF;

// ---------------- scratch ----------------
__device__ float d_xin[BTC];
__device__ float d_x1[BTC];
__device__ float d_q[BTC];
__device__ float d_k[BTC];
__device__ float d_v[BTC];
__device__ float d_ao[BTC];
__device__ float d_mhsa[BTC];
__device__ float d_res1[BTC];
__device__ float d_ci[Bb * C];
__device__ float d_ca[Bb * HW];
__device__ int   d_sel[Bb * NPOOL];
__device__ float d_x2[X2N];
__device__ float d_x2n[X2N];
__device__ float d_h1[H1N];

// ---------------- concat cls + x -> x_in ----------------
__global__ void concat_kernel(const float* __restrict__ x, const float* __restrict__ cls) {
    int idx = blockIdx.x * blockDim.x + threadIdx.x;
    if (idx >= BTC) return;
    int b = idx / (T * C);
    int rem = idx - b * (T * C);
    int t = rem / C;
    int c = rem - t * C;
    d_xin[idx] = (t == 0) ? cls[b * C + c] : x[((size_t)b * HW + (t - 1)) * C + c];
}

// ---------------- LayerNorm over (rows, C) per batch ----------------
__global__ void ln_kernel(const float* __restrict__ x, const float* __restrict__ w,
                          const float* __restrict__ bia, float* __restrict__ y, int rows) {
    int b = blockIdx.x;
    const float* xb = x + (size_t)b * rows * C;
    float* yb = y + (size_t)b * rows * C;
    int n = rows * C;
    float s = 0.f, s2 = 0.f;
    for (int i = threadIdx.x; i < n; i += blockDim.x) {
        float v = xb[i];
        s += v;
        s2 = fmaf(v, v, s2);
    }
    __shared__ float red1[32], red2[32];
    int lane = threadIdx.x & 31, wid = threadIdx.x >> 5;
    #pragma unroll
    for (int o = 16; o > 0; o >>= 1) {
        s  += __shfl_down_sync(0xffffffffu, s, o);
        s2 += __shfl_down_sync(0xffffffffu, s2, o);
    }
    if (lane == 0) { red1[wid] = s; red2[wid] = s2; }
    __syncthreads();
    __shared__ float mu_s, rs_s;
    if (threadIdx.x == 0) {
        float ts = 0.f, ts2 = 0.f;
        int nw = blockDim.x >> 5;
        for (int i = 0; i < nw; i++) { ts += red1[i]; ts2 += red2[i]; }
        float mu = ts / (float)n;
        float var = ts2 / (float)n - mu * mu;
        mu_s = mu;
        rs_s = rsqrtf(var + EPS);
    }
    __syncthreads();
    float mu = mu_s, rs = rs_s;
    for (int i = threadIdx.x; i < n; i += blockDim.x)
        yb[i] = (xb[i] - mu) * rs * w[i] + bia[i];
}

// ---------------- 128x128x32 NT GEMM, 8x8 per thread ----------------
// EPI 0: plain  1: exact GELU  2: Co=v, aux2=aux+v  3: v2=aux+v scatter to out
template <int EPI>
__global__ __launch_bounds__(256, 2) void gemm_nt(
        const float* __restrict__ A, const float* __restrict__ W,
        float* __restrict__ Co, int M, int N, int K,
        const float* __restrict__ aux, float* __restrict__ aux2) {
    __shared__ float As[32][132];
    __shared__ float Ws[32][132];
    int tid = threadIdx.x;
    int tm = tid >> 4, tn = tid & 15;
    int m0 = blockIdx.y * 128, n0 = blockIdx.x * 128;
    float acc[8][8];
    #pragma unroll
    for (int i = 0; i < 8; i++)
        #pragma unroll
        for (int j = 0; j < 8; j++) acc[i][j] = 0.f;

    for (int k0 = 0; k0 < K; k0 += 32) {
        #pragma unroll
        for (int i = 0; i < 4; i++) {
            int f = tid + i * 256;
            int r = f >> 3, c4 = (f & 7) * 4;
            int gm = m0 + r;
            float4 v = make_float4(0.f, 0.f, 0.f, 0.f);
            if (gm < M) v = *reinterpret_cast<const float4*>(A + (size_t)gm * K + k0 + c4);
            As[c4 + 0][r] = v.x; As[c4 + 1][r] = v.y;
            As[c4 + 2][r] = v.z; As[c4 + 3][r] = v.w;
        }
        #pragma unroll
        for (int i = 0; i < 4; i++) {
            int f = tid + i * 256;
            int r = f >> 3, c4 = (f & 7) * 4;
            int gn = n0 + r;  // N is always a multiple of 128 here
            float4 v = *reinterpret_cast<const float4*>(W + (size_t)gn * K + k0 + c4);
            Ws[c4 + 0][r] = v.x; Ws[c4 + 1][r] = v.y;
            Ws[c4 + 2][r] = v.z; Ws[c4 + 3][r] = v.w;
        }
        __syncthreads();
        #pragma unroll
        for (int kk = 0; kk < 32; kk++) {
            float4 a0 = *reinterpret_cast<const float4*>(&As[kk][tm * 8]);
            float4 a1 = *reinterpret_cast<const float4*>(&As[kk][tm * 8 + 4]);
            float4 b0 = *reinterpret_cast<const float4*>(&Ws[kk][tn * 8]);
            float4 b1 = *reinterpret_cast<const float4*>(&Ws[kk][tn * 8 + 4]);
            float a[8] = {a0.x, a0.y, a0.z, a0.w, a1.x, a1.y, a1.z, a1.w};
            float bb[8] = {b0.x, b0.y, b0.z, b0.w, b1.x, b1.y, b1.z, b1.w};
            #pragma unroll
            for (int i = 0; i < 8; i++)
                #pragma unroll
                for (int j = 0; j < 8; j++)
                    acc[i][j] = fmaf(a[i], bb[j], acc[i][j]);
        }
        __syncthreads();
    }

    #pragma unroll
    for (int i = 0; i < 8; i++) {
        int gm = m0 + tm * 8 + i;
        if (gm >= M) continue;
        #pragma unroll
        for (int j = 0; j < 8; j++) {
            int gn = n0 + tn * 8 + j;
            float v = acc[i][j];
            size_t idx = (size_t)gm * N + gn;
            if (EPI == 0) {
                Co[idx] = v;
            } else if (EPI == 1) {
                Co[idx] = 0.5f * v * (1.f + erff(v * 0.70710678118654752f));
            } else if (EPI == 2) {
                Co[idx] = v;
                aux2[idx] = aux[idx] + v;
            } else {
                float v2 = aux[idx] + v;
                int b = gm / TP;
                int t = gm - b * TP;
                if (t == 0)
                    aux2[(size_t)Bb * NPOOL * C + (size_t)b * C + gn] = v2;
                else
                    aux2[((size_t)b * NPOOL + (t - 1)) * C + gn] = v2;
            }
        }
    }
}

// ---------------- tiled flash attention: 64 queries / block, 128 threads ----------------
__global__ __launch_bounds__(128) void attn_kernel() {
    __shared__ float Qs[64][52];
    __shared__ float KVs[64][52];
    __shared__ float Ss[64][65];
    __shared__ float alpha_s[64], mrow[64], lrow[64];

    int q0 = blockIdx.x * 64, h = blockIdx.y, b = blockIdx.z;
    int t = threadIdx.x;
    const float scale = 0.14433756729740643f;  // 1/sqrt(48)

    // load Q tile (scaled); zero-fill invalid rows
    #pragma unroll
    for (int i = 0; i < 6; i++) {
        int f = t + i * 128;
        int r = f / 12, c = (f % 12) * 4;
        int gq = q0 + r;
        float4 v = make_float4(0.f, 0.f, 0.f, 0.f);
        if (gq < T) {
            v = *reinterpret_cast<const float4*>(d_q + ((size_t)b * T + gq) * C + h * HD + c);
            v.x *= scale; v.y *= scale; v.z *= scale; v.w *= scale;
        }
        *reinterpret_cast<float4*>(&Qs[r][c]) = v;
    }
    if (t < 64) { mrow[t] = -INFINITY; lrow[t] = 0.f; }

    // PV-phase ownership: 2 rows (rp, rp+32) x 12 cols
    int rp = t >> 2;
    int cg = (t & 3) * 12;
    float o0[12], o1[12];
    #pragma unroll
    for (int c = 0; c < 12; c++) { o0[c] = 0.f; o1[c] = 0.f; }

    // S-phase ownership: 8 rows x 4 cols
    int str = (t >> 4) * 8;
    int stc = (t & 15) * 4;
    // softmax ownership: 2 threads per row
    int rA = t >> 1, sub = t & 1;

    for (int kt = 0; kt < (T + 63) / 64; kt++) {
        int kbase = kt * 64;
        int nk = min(64, T - kbase);

        // load K tile
        #pragma unroll
        for (int i = 0; i < 6; i++) {
            int f = t + i * 128;
            int r = f / 12, c = (f % 12) * 4;
            int gk = kbase + r;
            float4 v = make_float4(0.f, 0.f, 0.f, 0.f);
            if (gk < T)
                v = *reinterpret_cast<const float4*>(d_k + ((size_t)b * T + gk) * C + h * HD + c);
            *reinterpret_cast<float4*>(&KVs[r][c]) = v;
        }
        __syncthreads();

        // S = Q K^T
        float sacc[8][4];
        #pragma unroll
        for (int i = 0; i < 8; i++)
            #pragma unroll
            for (int j = 0; j < 4; j++) sacc[i][j] = 0.f;
        #pragma unroll
        for (int k4 = 0; k4 < 48; k4 += 4) {
            float4 kb[4];
            #pragma unroll
            for (int j = 0; j < 4; j++)
                kb[j] = *reinterpret_cast<const float4*>(&KVs[stc + j][k4]);
            #pragma unroll
            for (int i = 0; i < 8; i++) {
                float4 qa = *reinterpret_cast<const float4*>(&Qs[str + i][k4]);
                #pragma unroll
                for (int j = 0; j < 4; j++) {
                    sacc[i][j] = fmaf(qa.x, kb[j].x, sacc[i][j]);
                    sacc[i][j] = fmaf(qa.y, kb[j].y, sacc[i][j]);
                    sacc[i][j] = fmaf(qa.z, kb[j].z, sacc[i][j]);
                    sacc[i][j] = fmaf(qa.w, kb[j].w, sacc[i][j]);
                }
            }
        }
        #pragma unroll
        for (int i = 0; i < 8; i++)
            #pragma unroll
            for (int j = 0; j < 4; j++)
                Ss[str + i][stc + j] = sacc[i][j];
        __syncthreads();

        // load V tile into KVs (K no longer needed)
        #pragma unroll
        for (int i = 0; i < 6; i++) {
            int f = t + i * 128;
            int r = f / 12, c = (f % 12) * 4;
            int gk = kbase + r;
            float4 v = make_float4(0.f, 0.f, 0.f, 0.f);
            if (gk < T)
                v = *reinterpret_cast<const float4*>(d_v + ((size_t)b * T + gk) * C + h * HD + c);
            *reinterpret_cast<float4*>(&KVs[r][c]) = v;
        }

        // online softmax (2 threads per row)
        {
            float mloc = -INFINITY;
            for (int j = sub; j < nk; j += 2) mloc = fmaxf(mloc, Ss[rA][j]);
            mloc = fmaxf(mloc, __shfl_xor_sync(0xffffffffu, mloc, 1));
            float mold = mrow[rA];
            float mnew = fmaxf(mold, mloc);
            float ls = 0.f;
            for (int j = sub; j < nk; j += 2) {
                float p = __expf(Ss[rA][j] - mnew);
                Ss[rA][j] = p;
                ls += p;
            }
            ls += __shfl_xor_sync(0xffffffffu, ls, 1);
            if (sub == 0) {
                float al = __expf(mold - mnew);
                mrow[rA] = mnew;
                lrow[rA] = lrow[rA] * al + ls;
                alpha_s[rA] = al;
            }
        }
        __syncthreads();

        // O rescale + P V
        float a0 = alpha_s[rp], a1 = alpha_s[rp + 32];
        #pragma unroll
        for (int c = 0; c < 12; c++) { o0[c] *= a0; o1[c] *= a1; }
        for (int j = 0; j < nk; j++) {
            float p0 = Ss[rp][j], p1 = Ss[rp + 32][j];
            float4 v0 = *reinterpret_cast<const float4*>(&KVs[j][cg]);
            float4 v1 = *reinterpret_cast<const float4*>(&KVs[j][cg + 4]);
            float4 v2 = *reinterpret_cast<const float4*>(&KVs[j][cg + 8]);
            float vv[12] = {v0.x, v0.y, v0.z, v0.w, v1.x, v1.y, v1.z, v1.w,
                            v2.x, v2.y, v2.z, v2.w};
            #pragma unroll
            for (int c = 0; c < 12; c++) {
                o0[c] = fmaf(p0, vv[c], o0[c]);
                o1[c] = fmaf(p1, vv[c], o1[c]);
            }
        }
        __syncthreads();
    }

    // write out
    int gq0 = q0 + rp, gq1 = q0 + rp + 32;
    if (gq0 < T) {
        float inv = 1.f / lrow[rp];
        float* op = d_ao + ((size_t)b * T + gq0) * C + h * HD + cg;
        #pragma unroll
        for (int c = 0; c < 12; c += 4) {
            float4 w = make_float4(o0[c] * inv, o0[c + 1] * inv, o0[c + 2] * inv, o0[c + 3] * inv);
            *reinterpret_cast<float4*>(op + c) = w;
        }
    }
    if (gq1 < T) {
        float inv = 1.f / lrow[rp + 32];
        float* op = d_ao + ((size_t)b * T + gq1) * C + h * HD + cg;
        #pragma unroll
        for (int c = 0; c < 12; c += 4) {
            float4 w = make_float4(o1[c] * inv, o1[c + 1] * inv, o1[c + 2] * inv, o1[c + 3] * inv);
            *reinterpret_cast<float4*>(op + c) = w;
        }
    }
}

// ---------------- ci = sigmoid(mean_t mhsa) ----------------
__global__ void ci_kernel() {
    int b = blockIdx.x;
    int c = threadIdx.x;
    float s = 0.f;
    for (int t = 0; t < T; t++) s += d_mhsa[((size_t)b * T + t) * C + c];
    float mu = s / (float)T;
    d_ci[b * C + c] = 1.f / (1.f + expf(-mu));
}

// ---------------- ca[b,n] = dot(nodes[b,n], ci[b]) ----------------
__global__ void ca_kernel() {
    int row = blockIdx.x * 8 + (threadIdx.x >> 5);
    int lane = threadIdx.x & 31;
    if (row >= Bb * HW) return;
    int b = row / HW, n = row - b * HW;
    const float* p = d_res1 + ((size_t)b * T + 1 + n) * C;
    const float* cc = d_ci + b * C;
    float s = 0.f;
    for (int i = lane; i < C; i += 32) s = fmaf(p[i], cc[i], s);
    #pragma unroll
    for (int o = 16; o > 0; o >>= 1) s += __shfl_down_sync(0xffffffffu, s, o);
    if (lane == 0) d_ca[row] = s;
}

// ---------------- stable ascending rank; keep top quarter ----------------
__global__ void rank_kernel() {
    int b = blockIdx.x;
    __shared__ float s[HW];
    for (int i = threadIdx.x; i < HW; i += blockDim.x) s[i] = d_ca[b * HW + i];
    __syncthreads();
    for (int n = threadIdx.x; n < HW; n += blockDim.x) {
        float v = s[n];
        int r = 0;
        for (int mm = 0; mm < HW; mm++) {
            float u = s[mm];
            r += (u < v) || (u == v && mm < n);
        }
        if (r >= CUT) d_sel[b * NPOOL + (r - CUT)] = n;
    }
}

// ---------------- gather x2 = [cls_row, pooled nodes] ----------------
__global__ void gather_kernel() {
    int idx = blockIdx.x * blockDim.x + threadIdx.x;
    if (idx >= X2N) return;
    int b = idx / (TP * C);
    int rem = idx - b * (TP * C);
    int t = rem / C;
    int c = rem - t * C;
    int srcrow = (t == 0) ? 0 : (1 + d_sel[b * NPOOL + t - 1]);
    d_x2[idx] = d_res1[((size_t)b * T + srcrow) * C + c];
}

// ---------------- launch ----------------
extern "C" void kernel_launch(void* const* d_in, const int* in_sizes, int n_in,
                              void* d_out, int out_size) {
    const float* x    = (const float*)d_in[0];
    const float* cls  = (const float*)d_in[1];
    const float* wln1 = (const float*)d_in[2];
    const float* bln1 = (const float*)d_in[3];
    const float* Wq   = (const float*)d_in[4];
    const float* Wk   = (const float*)d_in[5];
    const float* Wv   = (const float*)d_in[6];
    const float* Wo   = (const float*)d_in[7];
    const float* wln2 = (const float*)d_in[8];
    const float* bln2 = (const float*)d_in[9];
    const float* W1   = (const float*)d_in[10];
    const float* W2   = (const float*)d_in[11];
    float* out = (float*)d_out;

    float *p_xin, *p_x1, *p_q, *p_k, *p_v, *p_ao, *p_mhsa, *p_res1, *p_x2, *p_x2n, *p_h1;
    cudaGetSymbolAddress((void**)&p_xin,  d_xin);
    cudaGetSymbolAddress((void**)&p_x1,   d_x1);
    cudaGetSymbolAddress((void**)&p_q,    d_q);
    cudaGetSymbolAddress((void**)&p_k,    d_k);
    cudaGetSymbolAddress((void**)&p_v,    d_v);
    cudaGetSymbolAddress((void**)&p_ao,   d_ao);
    cudaGetSymbolAddress((void**)&p_mhsa, d_mhsa);
    cudaGetSymbolAddress((void**)&p_res1, d_res1);
    cudaGetSymbolAddress((void**)&p_x2,   d_x2);
    cudaGetSymbolAddress((void**)&p_x2n,  d_x2n);
    cudaGetSymbolAddress((void**)&p_h1,   d_h1);

    concat_kernel<<<(BTC + 255) / 256, 256>>>(x, cls);
    ln_kernel<<<Bb, 1024>>>(p_xin, wln1, bln1, p_x1, T);

    int Mqkv = Bb * T;
    dim3 gqkv(C / 128, (Mqkv + 127) / 128);
    gemm_nt<0><<<gqkv, 256>>>(p_x1, Wq, p_q, Mqkv, C, C, nullptr, nullptr);
    gemm_nt<0><<<gqkv, 256>>>(p_x1, Wk, p_k, Mqkv, C, C, nullptr, nullptr);
    gemm_nt<0><<<gqkv, 256>>>(p_x1, Wv, p_v, Mqkv, C, C, nullptr, nullptr);

    attn_kernel<<<dim3((T + 63) / 64, NH, Bb), 128>>>();

    gemm_nt<2><<<gqkv, 256>>>(p_ao, Wo, p_mhsa, Mqkv, C, C, p_xin, p_res1);

    ci_kernel<<<Bb, C>>>();
    ca_kernel<<<(Bb * HW + 7) / 8, 256>>>();
    rank_kernel<<<Bb, 256>>>();
    gather_kernel<<<(X2N + 255) / 256, 256>>>();

    ln_kernel<<<Bb, 1024>>>(p_x2, wln2, bln2, p_x2n, TP);

    int Mff = Bb * TP;
    gemm_nt<1><<<dim3(FF / 128, (Mff + 127) / 128), 256>>>(
        p_x2n, W1, p_h1, Mff, FF, C, nullptr, nullptr);
    gemm_nt<3><<<dim3(C / 128, (Mff + 127) / 128), 256>>>(
        p_h1, W2, nullptr, Mff, C, FF, p_x2n, out);
}

// round 4
// speedup vs baseline: 1.3024x; 1.0002x over previous
#include <cuda_runtime.h>
#include <math.h>

// ---------------- problem constants ----------------
constexpr int Bb = 32, HW = 784, C = 384, T = 785, TP = 197, FF = 1536;
constexpr int NH = 8, HD = 48;
constexpr int CUT = 588, NPOOL = 196;
constexpr float EPS = 1e-5f;

constexpr int BTC = Bb * T * C;
constexpr int X2N = Bb * TP * C;
constexpr int H1N = Bb * TP * FF;

// ---------------- scratch ----------------
__device__ float d_xin[BTC];
__device__ float d_x1[BTC];
__device__ float d_q[BTC];
__device__ float d_k[BTC];
__device__ float d_v[BTC];
__device__ float d_ao[BTC];
__device__ float d_mhsa[BTC];
__device__ float d_res1[BTC];
__device__ float d_cipart[Bb * 8 * C];
__device__ float d_ci[Bb * C];
__device__ float d_ca[Bb * HW];
__device__ int   d_sel[Bb * NPOOL];
__device__ float d_x2[X2N];
__device__ float d_x2n[X2N];
__device__ float d_h1[H1N];

// ---------------- fused concat + LayerNorm1 ----------------
// writes d_xin AND d_x1 in one kernel (one block per batch)
__global__ void concat_ln_kernel(const float* __restrict__ x, const float* __restrict__ cls,
                                 const float* __restrict__ w, const float* __restrict__ bia) {
    int b = blockIdx.x;
    float* xinb = d_xin + (size_t)b * T * C;
    float* yb = d_x1 + (size_t)b * T * C;
    constexpr int n = T * C;
    float s = 0.f, s2 = 0.f;
    for (int i = threadIdx.x; i < n; i += blockDim.x) {
        int t = i / C, c = i - t * C;
        float v = (t == 0) ? cls[b * C + c] : x[((size_t)b * HW + (t - 1)) * C + c];
        xinb[i] = v;
        s += v;
        s2 = fmaf(v, v, s2);
    }
    __shared__ float red1[32], red2[32];
    int lane = threadIdx.x & 31, wid = threadIdx.x >> 5;
    #pragma unroll
    for (int o = 16; o > 0; o >>= 1) {
        s  += __shfl_down_sync(0xffffffffu, s, o);
        s2 += __shfl_down_sync(0xffffffffu, s2, o);
    }
    if (lane == 0) { red1[wid] = s; red2[wid] = s2; }
    __syncthreads();
    __shared__ float mu_s, rs_s;
    if (threadIdx.x == 0) {
        float ts = 0.f, ts2 = 0.f;
        int nw = blockDim.x >> 5;
        for (int i = 0; i < nw; i++) { ts += red1[i]; ts2 += red2[i]; }
        float mu = ts / (float)n;
        float var = ts2 / (float)n - mu * mu;
        mu_s = mu;
        rs_s = rsqrtf(var + EPS);
    }
    __syncthreads();
    float mu = mu_s, rs = rs_s;
    for (int i = threadIdx.x; i < n; i += blockDim.x)
        yb[i] = (xinb[i] - mu) * rs * w[i] + bia[i];
}

// ---------------- LayerNorm over (rows, C) per batch ----------------
__global__ void ln_kernel(const float* __restrict__ x, const float* __restrict__ w,
                          const float* __restrict__ bia, float* __restrict__ y, int rows) {
    int b = blockIdx.x;
    const float* xb = x + (size_t)b * rows * C;
    float* yb = y + (size_t)b * rows * C;
    int n = rows * C;
    float s = 0.f, s2 = 0.f;
    for (int i = threadIdx.x; i < n; i += blockDim.x) {
        float v = xb[i];
        s += v;
        s2 = fmaf(v, v, s2);
    }
    __shared__ float red1[32], red2[32];
    int lane = threadIdx.x & 31, wid = threadIdx.x >> 5;
    #pragma unroll
    for (int o = 16; o > 0; o >>= 1) {
        s  += __shfl_down_sync(0xffffffffu, s, o);
        s2 += __shfl_down_sync(0xffffffffu, s2, o);
    }
    if (lane == 0) { red1[wid] = s; red2[wid] = s2; }
    __syncthreads();
    __shared__ float mu_s, rs_s;
    if (threadIdx.x == 0) {
        float ts = 0.f, ts2 = 0.f;
        int nw = blockDim.x >> 5;
        for (int i = 0; i < nw; i++) { ts += red1[i]; ts2 += red2[i]; }
        float mu = ts / (float)n;
        float var = ts2 / (float)n - mu * mu;
        mu_s = mu;
        rs_s = rsqrtf(var + EPS);
    }
    __syncthreads();
    float mu = mu_s, rs = rs_s;
    for (int i = threadIdx.x; i < n; i += blockDim.x)
        yb[i] = (xb[i] - mu) * rs * w[i] + bia[i];
}

// ---------------- 128x128x16 NT GEMM, double-buffered, 8x8 per thread ----------------
// EPI 0: plain  1: exact GELU  2: Co=v, aux2=aux+v  3: v2=aux+v scatter to out
template <int EPI>
__global__ __launch_bounds__(256, 2) void gemm_nt(
        const float* __restrict__ A, const float* __restrict__ W,
        float* __restrict__ Co, int M, int N, int K,
        const float* __restrict__ aux, float* __restrict__ aux2) {
    __shared__ float As[2][16][132];
    __shared__ float Ws[2][16][132];
    int tid = threadIdx.x;
    int tm = tid >> 4, tn = tid & 15;
    int m0 = blockIdx.y * 128, n0 = blockIdx.x * 128;
    float acc[8][8];
    #pragma unroll
    for (int i = 0; i < 8; i++)
        #pragma unroll
        for (int j = 0; j < 8; j++) acc[i][j] = 0.f;

    // staging indices: 2 float4 each for A and W per thread per tile
    int f0 = tid, f1 = tid + 256;
    int ra0 = f0 >> 2, ca0 = (f0 & 3) * 4;
    int ra1 = f1 >> 2, ca1 = (f1 & 3) * 4;
    bool am0 = (m0 + ra0) < M, am1 = (m0 + ra1) < M;
    const float* Ap0 = A + (size_t)(m0 + (am0 ? ra0 : 0)) * K + ca0;
    const float* Ap1 = A + (size_t)(m0 + (am1 ? ra1 : 0)) * K + ca1;
    const float* Wp0 = W + (size_t)(n0 + ra0) * K + ca0;   // N always multiple of 128
    const float* Wp1 = W + (size_t)(n0 + ra1) * K + ca1;

    float4 sa0, sa1, sw0, sw1;
    const float4 z4 = make_float4(0.f, 0.f, 0.f, 0.f);

    // preload tile 0
    sa0 = am0 ? *reinterpret_cast<const float4*>(Ap0) : z4;
    sa1 = am1 ? *reinterpret_cast<const float4*>(Ap1) : z4;
    sw0 = *reinterpret_cast<const float4*>(Wp0);
    sw1 = *reinterpret_cast<const float4*>(Wp1);
    As[0][ca0 + 0][ra0] = sa0.x; As[0][ca0 + 1][ra0] = sa0.y;
    As[0][ca0 + 2][ra0] = sa0.z; As[0][ca0 + 3][ra0] = sa0.w;
    As[0][ca1 + 0][ra1] = sa1.x; As[0][ca1 + 1][ra1] = sa1.y;
    As[0][ca1 + 2][ra1] = sa1.z; As[0][ca1 + 3][ra1] = sa1.w;
    Ws[0][ca0 + 0][ra0] = sw0.x; Ws[0][ca0 + 1][ra0] = sw0.y;
    Ws[0][ca0 + 2][ra0] = sw0.z; Ws[0][ca0 + 3][ra0] = sw0.w;
    Ws[0][ca1 + 0][ra1] = sw1.x; Ws[0][ca1 + 1][ra1] = sw1.y;
    Ws[0][ca1 + 2][ra1] = sw1.z; Ws[0][ca1 + 3][ra1] = sw1.w;
    __syncthreads();

    int nk = K >> 4;
    for (int kt = 0; kt < nk; kt++) {
        int cur = kt & 1;
        bool more = (kt + 1) < nk;
        if (more) {
            int ko = (kt + 1) << 4;
            sa0 = am0 ? *reinterpret_cast<const float4*>(Ap0 + ko) : z4;
            sa1 = am1 ? *reinterpret_cast<const float4*>(Ap1 + ko) : z4;
            sw0 = *reinterpret_cast<const float4*>(Wp0 + ko);
            sw1 = *reinterpret_cast<const float4*>(Wp1 + ko);
        }
        #pragma unroll
        for (int kk = 0; kk < 16; kk++) {
            float4 a0 = *reinterpret_cast<const float4*>(&As[cur][kk][tm * 8]);
            float4 a1 = *reinterpret_cast<const float4*>(&As[cur][kk][tm * 8 + 4]);
            float4 b0 = *reinterpret_cast<const float4*>(&Ws[cur][kk][tn * 8]);
            float4 b1 = *reinterpret_cast<const float4*>(&Ws[cur][kk][tn * 8 + 4]);
            float a[8] = {a0.x, a0.y, a0.z, a0.w, a1.x, a1.y, a1.z, a1.w};
            float bb[8] = {b0.x, b0.y, b0.z, b0.w, b1.x, b1.y, b1.z, b1.w};
            #pragma unroll
            for (int i = 0; i < 8; i++)
                #pragma unroll
                for (int j = 0; j < 8; j++)
                    acc[i][j] = fmaf(a[i], bb[j], acc[i][j]);
        }
        if (more) {
            int nxt = 1 - cur;
            As[nxt][ca0 + 0][ra0] = sa0.x; As[nxt][ca0 + 1][ra0] = sa0.y;
            As[nxt][ca0 + 2][ra0] = sa0.z; As[nxt][ca0 + 3][ra0] = sa0.w;
            As[nxt][ca1 + 0][ra1] = sa1.x; As[nxt][ca1 + 1][ra1] = sa1.y;
            As[nxt][ca1 + 2][ra1] = sa1.z; As[nxt][ca1 + 3][ra1] = sa1.w;
            Ws[nxt][ca0 + 0][ra0] = sw0.x; Ws[nxt][ca0 + 1][ra0] = sw0.y;
            Ws[nxt][ca0 + 2][ra0] = sw0.z; Ws[nxt][ca0 + 3][ra0] = sw0.w;
            Ws[nxt][ca1 + 0][ra1] = sw1.x; Ws[nxt][ca1 + 1][ra1] = sw1.y;
            Ws[nxt][ca1 + 2][ra1] = sw1.z; Ws[nxt][ca1 + 3][ra1] = sw1.w;
        }
        __syncthreads();
    }

    #pragma unroll
    for (int i = 0; i < 8; i++) {
        int gm = m0 + tm * 8 + i;
        if (gm >= M) continue;
        #pragma unroll
        for (int j = 0; j < 8; j++) {
            int gn = n0 + tn * 8 + j;
            float v = acc[i][j];
            size_t idx = (size_t)gm * N + gn;
            if (EPI == 0) {
                Co[idx] = v;
            } else if (EPI == 1) {
                Co[idx] = 0.5f * v * (1.f + erff(v * 0.70710678118654752f));
            } else if (EPI == 2) {
                Co[idx] = v;
                aux2[idx] = aux[idx] + v;
            } else {
                float v2 = aux[idx] + v;
                int b = gm / TP;
                int t = gm - b * TP;
                if (t == 0)
                    aux2[(size_t)Bb * NPOOL * C + (size_t)b * C + gn] = v2;
                else
                    aux2[((size_t)b * NPOOL + (t - 1)) * C + gn] = v2;
            }
        }
    }
}

// ---------------- tiled flash attention: 64 queries / block, 128 threads ----------------
__global__ __launch_bounds__(128) void attn_kernel() {
    __shared__ float Qs[64][52];
    __shared__ float KVs[64][52];
    __shared__ float Ss[64][65];
    __shared__ float alpha_s[64], mrow[64], lrow[64];

    int q0 = blockIdx.x * 64, h = blockIdx.y, b = blockIdx.z;
    int t = threadIdx.x;
    const float scale = 0.14433756729740643f;  // 1/sqrt(48)

    #pragma unroll
    for (int i = 0; i < 6; i++) {
        int f = t + i * 128;
        int r = f / 12, c = (f % 12) * 4;
        int gq = q0 + r;
        float4 v = make_float4(0.f, 0.f, 0.f, 0.f);
        if (gq < T) {
            v = *reinterpret_cast<const float4*>(d_q + ((size_t)b * T + gq) * C + h * HD + c);
            v.x *= scale; v.y *= scale; v.z *= scale; v.w *= scale;
        }
        *reinterpret_cast<float4*>(&Qs[r][c]) = v;
    }
    if (t < 64) { mrow[t] = -INFINITY; lrow[t] = 0.f; }

    int rp = t >> 2;
    int cg = (t & 3) * 12;
    float o0[12], o1[12];
    #pragma unroll
    for (int c = 0; c < 12; c++) { o0[c] = 0.f; o1[c] = 0.f; }

    int str = (t >> 4) * 8;
    int stc = (t & 15) * 4;
    int rA = t >> 1, sub = t & 1;

    for (int kt = 0; kt < (T + 63) / 64; kt++) {
        int kbase = kt * 64;
        int nk = min(64, T - kbase);

        #pragma unroll
        for (int i = 0; i < 6; i++) {
            int f = t + i * 128;
            int r = f / 12, c = (f % 12) * 4;
            int gk = kbase + r;
            float4 v = make_float4(0.f, 0.f, 0.f, 0.f);
            if (gk < T)
                v = *reinterpret_cast<const float4*>(d_k + ((size_t)b * T + gk) * C + h * HD + c);
            *reinterpret_cast<float4*>(&KVs[r][c]) = v;
        }
        __syncthreads();

        float sacc[8][4];
        #pragma unroll
        for (int i = 0; i < 8; i++)
            #pragma unroll
            for (int j = 0; j < 4; j++) sacc[i][j] = 0.f;
        #pragma unroll
        for (int k4 = 0; k4 < 48; k4 += 4) {
            float4 kb[4];
            #pragma unroll
            for (int j = 0; j < 4; j++)
                kb[j] = *reinterpret_cast<const float4*>(&KVs[stc + j][k4]);
            #pragma unroll
            for (int i = 0; i < 8; i++) {
                float4 qa = *reinterpret_cast<const float4*>(&Qs[str + i][k4]);
                #pragma unroll
                for (int j = 0; j < 4; j++) {
                    sacc[i][j] = fmaf(qa.x, kb[j].x, sacc[i][j]);
                    sacc[i][j] = fmaf(qa.y, kb[j].y, sacc[i][j]);
                    sacc[i][j] = fmaf(qa.z, kb[j].z, sacc[i][j]);
                    sacc[i][j] = fmaf(qa.w, kb[j].w, sacc[i][j]);
                }
            }
        }
        #pragma unroll
        for (int i = 0; i < 8; i++)
            #pragma unroll
            for (int j = 0; j < 4; j++)
                Ss[str + i][stc + j] = sacc[i][j];
        __syncthreads();

        #pragma unroll
        for (int i = 0; i < 6; i++) {
            int f = t + i * 128;
            int r = f / 12, c = (f % 12) * 4;
            int gk = kbase + r;
            float4 v = make_float4(0.f, 0.f, 0.f, 0.f);
            if (gk < T)
                v = *reinterpret_cast<const float4*>(d_v + ((size_t)b * T + gk) * C + h * HD + c);
            *reinterpret_cast<float4*>(&KVs[r][c]) = v;
        }

        {
            float mloc = -INFINITY;
            for (int j = sub; j < nk; j += 2) mloc = fmaxf(mloc, Ss[rA][j]);
            mloc = fmaxf(mloc, __shfl_xor_sync(0xffffffffu, mloc, 1));
            float mold = mrow[rA];
            float mnew = fmaxf(mold, mloc);
            float ls = 0.f;
            for (int j = sub; j < nk; j += 2) {
                float p = __expf(Ss[rA][j] - mnew);
                Ss[rA][j] = p;
                ls += p;
            }
            ls += __shfl_xor_sync(0xffffffffu, ls, 1);
            if (sub == 0) {
                float al = __expf(mold - mnew);
                mrow[rA] = mnew;
                lrow[rA] = lrow[rA] * al + ls;
                alpha_s[rA] = al;
            }
        }
        __syncthreads();

        float a0 = alpha_s[rp], a1 = alpha_s[rp + 32];
        #pragma unroll
        for (int c = 0; c < 12; c++) { o0[c] *= a0; o1[c] *= a1; }
        for (int j = 0; j < nk; j++) {
            float p0 = Ss[rp][j], p1 = Ss[rp + 32][j];
            float4 v0 = *reinterpret_cast<const float4*>(&KVs[j][cg]);
            float4 v1 = *reinterpret_cast<const float4*>(&KVs[j][cg + 4]);
            float4 v2 = *reinterpret_cast<const float4*>(&KVs[j][cg + 8]);
            float vv[12] = {v0.x, v0.y, v0.z, v0.w, v1.x, v1.y, v1.z, v1.w,
                            v2.x, v2.y, v2.z, v2.w};
            #pragma unroll
            for (int c = 0; c < 12; c++) {
                o0[c] = fmaf(p0, vv[c], o0[c]);
                o1[c] = fmaf(p1, vv[c], o1[c]);
            }
        }
        __syncthreads();
    }

    int gq0 = q0 + rp, gq1 = q0 + rp + 32;
    if (gq0 < T) {
        float inv = 1.f / lrow[rp];
        float* op = d_ao + ((size_t)b * T + gq0) * C + h * HD + cg;
        #pragma unroll
        for (int c = 0; c < 12; c += 4) {
            float4 w = make_float4(o0[c] * inv, o0[c + 1] * inv, o0[c + 2] * inv, o0[c + 3] * inv);
            *reinterpret_cast<float4*>(op + c) = w;
        }
    }
    if (gq1 < T) {
        float inv = 1.f / lrow[rp + 32];
        float* op = d_ao + ((size_t)b * T + gq1) * C + h * HD + cg;
        #pragma unroll
        for (int c = 0; c < 12; c += 4) {
            float4 w = make_float4(o1[c] * inv, o1[c + 1] * inv, o1[c + 2] * inv, o1[c + 3] * inv);
            *reinterpret_cast<float4*>(op + c) = w;
        }
    }
}

// ---------------- ci stage 1: partial column sums of mhsa ----------------
__global__ void ci_part_kernel() {
    int b = blockIdx.x, chunk = blockIdx.y;
    int c = threadIdx.x;
    int t0 = chunk * 99, t1 = min(T, t0 + 99);
    float s = 0.f;
    for (int t = t0; t < t1; t++) s += d_mhsa[((size_t)b * T + t) * C + c];
    d_cipart[((size_t)b * 8 + chunk) * C + c] = s;
}

// ---------------- ci stage 2: combine + sigmoid ----------------
__global__ void ci_final_kernel() {
    int b = blockIdx.x;
    int c = threadIdx.x;
    float s = 0.f;
    #pragma unroll
    for (int k = 0; k < 8; k++) s += d_cipart[((size_t)b * 8 + k) * C + c];
    float mu = s / (float)T;
    d_ci[b * C + c] = 1.f / (1.f + expf(-mu));
}

// ---------------- ca[b,n] = dot(nodes[b,n], ci[b]) ----------------
__global__ void ca_kernel() {
    int row = blockIdx.x * 8 + (threadIdx.x >> 5);
    int lane = threadIdx.x & 31;
    if (row >= Bb * HW) return;
    int b = row / HW, n = row - b * HW;
    const float* p = d_res1 + ((size_t)b * T + 1 + n) * C;
    const float* cc = d_ci + b * C;
    float s = 0.f;
    for (int i = lane; i < C; i += 32) s = fmaf(p[i], cc[i], s);
    #pragma unroll
    for (int o = 16; o > 0; o >>= 1) s += __shfl_down_sync(0xffffffffu, s, o);
    if (lane == 0) d_ca[row] = s;
}

// ---------------- stable ascending rank; keep top quarter ----------------
__global__ void rank_kernel() {
    int b = blockIdx.x;
    __shared__ float s[HW];
    for (int i = threadIdx.x; i < HW; i += blockDim.x) s[i] = d_ca[b * HW + i];
    __syncthreads();
    for (int n = threadIdx.x; n < HW; n += blockDim.x) {
        float v = s[n];
        int r = 0;
        for (int mm = 0; mm < HW; mm++) {
            float u = s[mm];
            r += (u < v) || (u == v && mm < n);
        }
        if (r >= CUT) d_sel[b * NPOOL + (r - CUT)] = n;
    }
}

// ---------------- gather x2 = [cls_row, pooled nodes] ----------------
__global__ void gather_kernel() {
    int idx = blockIdx.x * blockDim.x + threadIdx.x;
    if (idx >= X2N) return;
    int b = idx / (TP * C);
    int rem = idx - b * (TP * C);
    int t = rem / C;
    int c = rem - t * C;
    int srcrow = (t == 0) ? 0 : (1 + d_sel[b * NPOOL + t - 1]);
    d_x2[idx] = d_res1[((size_t)b * T + srcrow) * C + c];
}

// ---------------- launch ----------------
extern "C" void kernel_launch(void* const* d_in, const int* in_sizes, int n_in,
                              void* d_out, int out_size) {
    const float* x    = (const float*)d_in[0];
    const float* cls  = (const float*)d_in[1];
    const float* wln1 = (const float*)d_in[2];
    const float* bln1 = (const float*)d_in[3];
    const float* Wq   = (const float*)d_in[4];
    const float* Wk   = (const float*)d_in[5];
    const float* Wv   = (const float*)d_in[6];
    const float* Wo   = (const float*)d_in[7];
    const float* wln2 = (const float*)d_in[8];
    const float* bln2 = (const float*)d_in[9];
    const float* W1   = (const float*)d_in[10];
    const float* W2   = (const float*)d_in[11];
    float* out = (float*)d_out;

    float *p_xin, *p_x1, *p_q, *p_k, *p_v, *p_ao, *p_mhsa, *p_res1, *p_x2, *p_x2n, *p_h1;
    cudaGetSymbolAddress((void**)&p_xin,  d_xin);
    cudaGetSymbolAddress((void**)&p_x1,   d_x1);
    cudaGetSymbolAddress((void**)&p_q,    d_q);
    cudaGetSymbolAddress((void**)&p_k,    d_k);
    cudaGetSymbolAddress((void**)&p_v,    d_v);
    cudaGetSymbolAddress((void**)&p_ao,   d_ao);
    cudaGetSymbolAddress((void**)&p_mhsa, d_mhsa);
    cudaGetSymbolAddress((void**)&p_res1, d_res1);
    cudaGetSymbolAddress((void**)&p_x2,   d_x2);
    cudaGetSymbolAddress((void**)&p_x2n,  d_x2n);
    cudaGetSymbolAddress((void**)&p_h1,   d_h1);

    concat_ln_kernel<<<Bb, 1024>>>(x, cls, wln1, bln1);

    int Mqkv = Bb * T;
    dim3 gqkv(C / 128, (Mqkv + 127) / 128);
    gemm_nt<0><<<gqkv, 256>>>(p_x1, Wq, p_q, Mqkv, C, C, nullptr, nullptr);
    gemm_nt<0><<<gqkv, 256>>>(p_x1, Wk, p_k, Mqkv, C, C, nullptr, nullptr);
    gemm_nt<0><<<gqkv, 256>>>(p_x1, Wv, p_v, Mqkv, C, C, nullptr, nullptr);

    attn_kernel<<<dim3((T + 63) / 64, NH, Bb), 128>>>();

    gemm_nt<2><<<gqkv, 256>>>(p_ao, Wo, p_mhsa, Mqkv, C, C, p_xin, p_res1);

    ci_part_kernel<<<dim3(Bb, 8), C>>>();
    ci_final_kernel<<<Bb, C>>>();
    ca_kernel<<<(Bb * HW + 7) / 8, 256>>>();
    rank_kernel<<<Bb, 256>>>();
    gather_kernel<<<(X2N + 255) / 256, 256>>>();

    ln_kernel<<<Bb, 1024>>>(p_x2, wln2, bln2, p_x2n, TP);

    int Mff = Bb * TP;
    gemm_nt<1><<<dim3(FF / 128, (Mff + 127) / 128), 256>>>(
        p_x2n, W1, p_h1, Mff, FF, C, nullptr, nullptr);
    gemm_nt<3><<<dim3(C / 128, (Mff + 127) / 128), 256>>>(
        p_h1, W2, nullptr, Mff, C, FF, p_x2n, out);
}

// round 16
// speedup vs baseline: 1.3796x; 1.0592x over previous
#include <cuda_runtime.h>
#include <cuda_bf16.h>
#include <math.h>
#include <stdint.h>

// ---------------- problem constants ----------------
constexpr int Bb = 32, HW = 784, C = 384, T = 785, TP = 197, FF = 1536;
constexpr int NH = 8, HD = 48;
constexpr int CUT = 588, NPOOL = 196;
constexpr float EPS = 1e-5f;

constexpr int BTC = Bb * T * C;
constexpr int X2N = Bb * TP * C;
constexpr int H1N = Bb * TP * FF;
constexpr int MTOK = Bb * T;     // 25120
constexpr int MP   = Bb * TP;    // 6304

// ---------------- fp32 scratch ----------------
__device__ float d_xin[BTC];
__device__ float d_x1[BTC];
__device__ float d_q[BTC];
__device__ float d_k[BTC];
__device__ float d_v[BTC];
__device__ float d_ao[BTC];
__device__ float d_mhsa[BTC];
__device__ float d_res1[BTC];
__device__ float d_cipart[Bb * 8 * C];
__device__ float d_ci[Bb * C];
__device__ float d_ca[Bb * HW];
__device__ int   d_sel[Bb * NPOOL];
__device__ float d_x2[X2N];
__device__ float d_x2n[X2N];
__device__ float d_h1[H1N];

// ---------------- bf16 split scratch (FFN only; K' = 3K concat) ----------------
__device__ __nv_bfloat16 s_x2n[(size_t)MP * 3 * C];
__device__ __nv_bfloat16 s_w1 [(size_t)FF * 3 * C];
__device__ __nv_bfloat16 s_h1 [(size_t)MP * 3 * FF];
__device__ __nv_bfloat16 s_w2 [(size_t)C * 3 * FF];

// ---------------- fp32 SIMT NT GEMM (round-3 proven, 128x128x32, 8x8/thr) ----
// EPI 0: plain   2: Co=v, aux2=aux+v (Wo+residual)
template <int EPI>
__global__ __launch_bounds__(256, 2) void gemm_nt(
        const float* __restrict__ A, const float* __restrict__ W,
        float* __restrict__ Co, int M, int N, int K,
        const float* __restrict__ aux, float* __restrict__ aux2) {
    __shared__ float As[32][132];
    __shared__ float Ws[32][132];
    int tid = threadIdx.x;
    int tm = tid >> 4, tn = tid & 15;
    int m0 = blockIdx.y * 128, n0 = blockIdx.x * 128;
    float acc[8][8];
    #pragma unroll
    for (int i = 0; i < 8; i++)
        #pragma unroll
        for (int j = 0; j < 8; j++) acc[i][j] = 0.f;

    for (int k0 = 0; k0 < K; k0 += 32) {
        #pragma unroll
        for (int i = 0; i < 4; i++) {
            int f = tid + i * 256;
            int r = f >> 3, c4 = (f & 7) * 4;
            int gm = m0 + r;
            float4 v = make_float4(0.f, 0.f, 0.f, 0.f);
            if (gm < M) v = *reinterpret_cast<const float4*>(A + (size_t)gm * K + k0 + c4);
            As[c4 + 0][r] = v.x; As[c4 + 1][r] = v.y;
            As[c4 + 2][r] = v.z; As[c4 + 3][r] = v.w;
        }
        #pragma unroll
        for (int i = 0; i < 4; i++) {
            int f = tid + i * 256;
            int r = f >> 3, c4 = (f & 7) * 4;
            int gn = n0 + r;  // N multiple of 128
            float4 v = *reinterpret_cast<const float4*>(W + (size_t)gn * K + k0 + c4);
            Ws[c4 + 0][r] = v.x; Ws[c4 + 1][r] = v.y;
            Ws[c4 + 2][r] = v.z; Ws[c4 + 3][r] = v.w;
        }
        __syncthreads();
        #pragma unroll
        for (int kk = 0; kk < 32; kk++) {
            float4 a0 = *reinterpret_cast<const float4*>(&As[kk][tm * 8]);
            float4 a1 = *reinterpret_cast<const float4*>(&As[kk][tm * 8 + 4]);
            float4 b0 = *reinterpret_cast<const float4*>(&Ws[kk][tn * 8]);
            float4 b1 = *reinterpret_cast<const float4*>(&Ws[kk][tn * 8 + 4]);
            float a[8] = {a0.x, a0.y, a0.z, a0.w, a1.x, a1.y, a1.z, a1.w};
            float bb[8] = {b0.x, b0.y, b0.z, b0.w, b1.x, b1.y, b1.z, b1.w};
            #pragma unroll
            for (int i = 0; i < 8; i++)
                #pragma unroll
                for (int j = 0; j < 8; j++)
                    acc[i][j] = fmaf(a[i], bb[j], acc[i][j]);
        }
        __syncthreads();
    }

    #pragma unroll
    for (int i = 0; i < 8; i++) {
        int gm = m0 + tm * 8 + i;
        if (gm >= M) continue;
        #pragma unroll
        for (int j = 0; j < 8; j++) {
            int gn = n0 + tn * 8 + j;
            float v = acc[i][j];
            size_t idx = (size_t)gm * N + gn;
            if (EPI == 0) {
                Co[idx] = v;
            } else {  // EPI 2
                Co[idx] = v;
                aux2[idx] = aux[idx] + v;
            }
        }
    }
}

// ---------------- mma.sync helpers (tensor path on sm_103) ----------------
__device__ __forceinline__ uint32_t smem_u32(const void* p) {
    return (uint32_t)__cvta_generic_to_shared(p);
}
__device__ __forceinline__ void ldmat4(uint32_t r[4], uint32_t addr) {
    asm volatile("ldmatrix.sync.aligned.m8n8.x4.shared.b16 {%0,%1,%2,%3}, [%4];"
        : "=r"(r[0]), "=r"(r[1]), "=r"(r[2]), "=r"(r[3]) : "r"(addr));
}
__device__ __forceinline__ void mma16816(float d[4], const uint32_t a[4],
                                         const uint32_t b[2]) {
    asm volatile(
        "mma.sync.aligned.m16n8k16.row.col.f32.bf16.bf16.f32 "
        "{%0,%1,%2,%3}, {%4,%5,%6,%7}, {%8,%9}, {%0,%1,%2,%3};"
        : "+f"(d[0]), "+f"(d[1]), "+f"(d[2]), "+f"(d[3])
        : "r"(a[0]), "r"(a[1]), "r"(a[2]), "r"(a[3]), "r"(b[0]), "r"(b[1]));
}

// ---------------- asymmetric 3-term splits (round-12 exercised path) --------
// activation: [hi | hi | lo];  weight: [hi | lo | hi]
// => products hi*hi + hi*lo + lo*hi (drop lo*lo ~2^-18 rel; value-safe for FFN)
__global__ void split_act_kernel(const float* __restrict__ A,
                                 __nv_bfloat16* __restrict__ O, int M, int K) {
    int idx = blockIdx.x * 256 + threadIdx.x;
    if (idx >= M * K) return;
    int r = idx / K, k = idx - r * K;
    float a = A[idx];
    __nv_bfloat16 hi = __float2bfloat16(a);
    __nv_bfloat16 lo = __float2bfloat16(a - __bfloat162float(hi));
    size_t base = (size_t)r * 3 * K + k;
    O[base] = hi;
    O[base + K] = hi;
    O[base + 2 * K] = lo;
}
__global__ void split_wt_kernel(const float* __restrict__ A,
                                __nv_bfloat16* __restrict__ O, int M, int K) {
    int idx = blockIdx.x * 256 + threadIdx.x;
    if (idx >= M * K) return;
    int r = idx / K, k = idx - r * K;
    float a = A[idx];
    __nv_bfloat16 hi = __float2bfloat16(a);
    __nv_bfloat16 lo = __float2bfloat16(a - __bfloat162float(hi));
    size_t base = (size_t)r * 3 * K + k;
    O[base] = hi;
    O[base + K] = lo;
    O[base + 2 * K] = hi;
}

// ---------------- tensor-op NT GEMM (FFN only): D = A(Kp) x B(Kp)^T --------
// block 128x128, warp 64x32, K-chunk 32 bf16. EPI 1: exact GELU  3: FFN2 scatter
constexpr int LDT = 40;  // bf16 row stride in smem (80 bytes)

template <int EPI>
__global__ __launch_bounds__(256) void gemm_mma(
        const __nv_bfloat16* __restrict__ A, const __nv_bfloat16* __restrict__ Bw,
        float* __restrict__ Co, int M, int N, int Kp,
        const float* __restrict__ aux, float* __restrict__ aux2) {
    __shared__ __nv_bfloat16 As[128 * LDT];
    __shared__ __nv_bfloat16 Bs[128 * LDT];
    int tid = threadIdx.x;
    int wid = tid >> 5, lane = tid & 31;
    int wm = wid >> 2, wn = wid & 3;
    int m0 = blockIdx.y * 128, n0 = blockIdx.x * 128;

    float acc[4][4][4];
    #pragma unroll
    for (int i = 0; i < 4; i++)
        #pragma unroll
        for (int j = 0; j < 4; j++)
            #pragma unroll
            for (int e = 0; e < 4; e++) acc[i][j][e] = 0.f;

    uint32_t aBase = smem_u32(As), bBase = smem_u32(Bs);

    int rlA = (lane & 7) + 8 * ((lane >> 3) & 1);
    int ksA = 8 * ((lane >> 4) & 1);
    int rlB = (lane & 7) + 8 * ((lane >> 4) & 1);
    int ksB = 8 * ((lane >> 3) & 1);

    int r0 = tid >> 2, s0 = (tid & 3) * 8;
    int r1 = r0 + 64;

    int nchunk = Kp >> 5;
    for (int kc = 0; kc < nchunk; kc++) {
        int kb = kc * 32;
        {
            int gm = m0 + r0;
            uint4 v = make_uint4(0, 0, 0, 0);
            if (gm < M) v = *reinterpret_cast<const uint4*>(A + (size_t)gm * Kp + kb + s0);
            *reinterpret_cast<uint4*>(&As[r0 * LDT + s0]) = v;
            gm = m0 + r1;
            v = make_uint4(0, 0, 0, 0);
            if (gm < M) v = *reinterpret_cast<const uint4*>(A + (size_t)gm * Kp + kb + s0);
            *reinterpret_cast<uint4*>(&As[r1 * LDT + s0]) = v;
            v = *reinterpret_cast<const uint4*>(Bw + (size_t)(n0 + r0) * Kp + kb + s0);
            *reinterpret_cast<uint4*>(&Bs[r0 * LDT + s0]) = v;
            v = *reinterpret_cast<const uint4*>(Bw + (size_t)(n0 + r1) * Kp + kb + s0);
            *reinterpret_cast<uint4*>(&Bs[r1 * LDT + s0]) = v;
        }
        __syncthreads();
        #pragma unroll
        for (int ks = 0; ks < 2; ks++) {
            uint32_t af[4][4], bf[2][4];
            #pragma unroll
            for (int mi = 0; mi < 4; mi++) {
                int row = wm * 64 + mi * 16 + rlA;
                ldmat4(af[mi], aBase + (row * LDT + ks * 16 + ksA) * 2);
            }
            #pragma unroll
            for (int np = 0; np < 2; np++) {
                int row = wn * 32 + np * 16 + rlB;
                ldmat4(bf[np], bBase + (row * LDT + ks * 16 + ksB) * 2);
            }
            #pragma unroll
            for (int mi = 0; mi < 4; mi++) {
                #pragma unroll
                for (int np = 0; np < 2; np++) {
                    mma16816(acc[mi][np * 2 + 0], af[mi], &bf[np][0]);
                    mma16816(acc[mi][np * 2 + 1], af[mi], &bf[np][2]);
                }
            }
        }
        __syncthreads();
    }

    int rbase = m0 + wm * 64 + (lane >> 2);
    int cbase = n0 + wn * 32 + (lane & 3) * 2;
    #pragma unroll
    for (int mi = 0; mi < 4; mi++) {
        #pragma unroll
        for (int half = 0; half < 2; half++) {
            int gm = rbase + mi * 16 + half * 8;
            if (gm >= M) continue;
            #pragma unroll
            for (int nj = 0; nj < 4; nj++) {
                #pragma unroll
                for (int e = 0; e < 2; e++) {
                    int gn = cbase + nj * 8 + e;
                    float v = acc[mi][nj][half * 2 + e];
                    size_t idx = (size_t)gm * N + gn;
                    if (EPI == 1) {
                        Co[idx] = 0.5f * v * (1.f + erff(v * 0.70710678118654752f));
                    } else {  // EPI 3: v2 = aux + v, scatter to output
                        float v2 = aux[idx] + v;
                        int b = gm / TP, tt = gm - b * TP;
                        if (tt == 0)
                            aux2[(size_t)Bb * NPOOL * C + (size_t)b * C + gn] = v2;
                        else
                            aux2[((size_t)b * NPOOL + (tt - 1)) * C + gn] = v2;
                    }
                }
            }
        }
    }
}

// ---------------- fused concat + LayerNorm1 ----------------
__global__ void concat_ln_kernel(const float* __restrict__ x, const float* __restrict__ cls,
                                 const float* __restrict__ w, const float* __restrict__ bia) {
    int b = blockIdx.x;
    float* xinb = d_xin + (size_t)b * T * C;
    float* yb = d_x1 + (size_t)b * T * C;
    constexpr int n = T * C;
    float s = 0.f, s2 = 0.f;
    for (int i = threadIdx.x; i < n; i += blockDim.x) {
        int t = i / C, c = i - t * C;
        float v = (t == 0) ? cls[b * C + c] : x[((size_t)b * HW + (t - 1)) * C + c];
        xinb[i] = v;
        s += v;
        s2 = fmaf(v, v, s2);
    }
    __shared__ float red1[32], red2[32];
    int lane = threadIdx.x & 31, wid = threadIdx.x >> 5;
    #pragma unroll
    for (int o = 16; o > 0; o >>= 1) {
        s  += __shfl_down_sync(0xffffffffu, s, o);
        s2 += __shfl_down_sync(0xffffffffu, s2, o);
    }
    if (lane == 0) { red1[wid] = s; red2[wid] = s2; }
    __syncthreads();
    __shared__ float mu_s, rs_s;
    if (threadIdx.x == 0) {
        float ts = 0.f, ts2 = 0.f;
        int nw = blockDim.x >> 5;
        for (int i = 0; i < nw; i++) { ts += red1[i]; ts2 += red2[i]; }
        float mu = ts / (float)n;
        float var = ts2 / (float)n - mu * mu;
        mu_s = mu;
        rs_s = rsqrtf(var + EPS);
    }
    __syncthreads();
    float mu = mu_s, rs = rs_s;
    for (int i = threadIdx.x; i < n; i += blockDim.x)
        yb[i] = (xinb[i] - mu) * rs * w[i] + bia[i];
}

// ---------------- LayerNorm ----------------
__global__ void ln_kernel(const float* __restrict__ x, const float* __restrict__ w,
                          const float* __restrict__ bia, float* __restrict__ y, int rows) {
    int b = blockIdx.x;
    const float* xb = x + (size_t)b * rows * C;
    float* yb = y + (size_t)b * rows * C;
    int n = rows * C;
    float s = 0.f, s2 = 0.f;
    for (int i = threadIdx.x; i < n; i += blockDim.x) {
        float v = xb[i];
        s += v;
        s2 = fmaf(v, v, s2);
    }
    __shared__ float red1[32], red2[32];
    int lane = threadIdx.x & 31, wid = threadIdx.x >> 5;
    #pragma unroll
    for (int o = 16; o > 0; o >>= 1) {
        s  += __shfl_down_sync(0xffffffffu, s, o);
        s2 += __shfl_down_sync(0xffffffffu, s2, o);
    }
    if (lane == 0) { red1[wid] = s; red2[wid] = s2; }
    __syncthreads();
    __shared__ float mu_s, rs_s;
    if (threadIdx.x == 0) {
        float ts = 0.f, ts2 = 0.f;
        int nw = blockDim.x >> 5;
        for (int i = 0; i < nw; i++) { ts += red1[i]; ts2 += red2[i]; }
        float mu = ts / (float)n;
        float var = ts2 / (float)n - mu * mu;
        mu_s = mu;
        rs_s = rsqrtf(var + EPS);
    }
    __syncthreads();
    float mu = mu_s, rs = rs_s;
    for (int i = threadIdx.x; i < n; i += blockDim.x)
        yb[i] = (xb[i] - mu) * rs * w[i] + bia[i];
}

// ---------------- flash attention (known-good fp32) ----------------
__global__ __launch_bounds__(128) void attn_kernel() {
    __shared__ float Qs[64][52];
    __shared__ float KVs[64][52];
    __shared__ float Ss[64][65];
    __shared__ float alpha_s[64], mrow[64], lrow[64];

    int q0 = blockIdx.x * 64, h = blockIdx.y, b = blockIdx.z;
    int t = threadIdx.x;
    const float scale = 0.14433756729740643f;

    #pragma unroll
    for (int i = 0; i < 6; i++) {
        int f = t + i * 128;
        int r = f / 12, c = (f % 12) * 4;
        int gq = q0 + r;
        float4 v = make_float4(0.f, 0.f, 0.f, 0.f);
        if (gq < T) {
            v = *reinterpret_cast<const float4*>(d_q + ((size_t)b * T + gq) * C + h * HD + c);
            v.x *= scale; v.y *= scale; v.z *= scale; v.w *= scale;
        }
        *reinterpret_cast<float4*>(&Qs[r][c]) = v;
    }
    if (t < 64) { mrow[t] = -INFINITY; lrow[t] = 0.f; }

    int rp = t >> 2;
    int cg = (t & 3) * 12;
    float o0[12], o1[12];
    #pragma unroll
    for (int c = 0; c < 12; c++) { o0[c] = 0.f; o1[c] = 0.f; }

    int str = (t >> 4) * 8;
    int stc = (t & 15) * 4;
    int rA = t >> 1, sub = t & 1;

    for (int kt = 0; kt < (T + 63) / 64; kt++) {
        int kbase = kt * 64;
        int nk = min(64, T - kbase);

        #pragma unroll
        for (int i = 0; i < 6; i++) {
            int f = t + i * 128;
            int r = f / 12, c = (f % 12) * 4;
            int gk = kbase + r;
            float4 v = make_float4(0.f, 0.f, 0.f, 0.f);
            if (gk < T)
                v = *reinterpret_cast<const float4*>(d_k + ((size_t)b * T + gk) * C + h * HD + c);
            *reinterpret_cast<float4*>(&KVs[r][c]) = v;
        }
        __syncthreads();

        float sacc[8][4];
        #pragma unroll
        for (int i = 0; i < 8; i++)
            #pragma unroll
            for (int j = 0; j < 4; j++) sacc[i][j] = 0.f;
        #pragma unroll
        for (int k4 = 0; k4 < 48; k4 += 4) {
            float4 kb[4];
            #pragma unroll
            for (int j = 0; j < 4; j++)
                kb[j] = *reinterpret_cast<const float4*>(&KVs[stc + j][k4]);
            #pragma unroll
            for (int i = 0; i < 8; i++) {
                float4 qa = *reinterpret_cast<const float4*>(&Qs[str + i][k4]);
                #pragma unroll
                for (int j = 0; j < 4; j++) {
                    sacc[i][j] = fmaf(qa.x, kb[j].x, sacc[i][j]);
                    sacc[i][j] = fmaf(qa.y, kb[j].y, sacc[i][j]);
                    sacc[i][j] = fmaf(qa.z, kb[j].z, sacc[i][j]);
                    sacc[i][j] = fmaf(qa.w, kb[j].w, sacc[i][j]);
                }
            }
        }
        #pragma unroll
        for (int i = 0; i < 8; i++)
            #pragma unroll
            for (int j = 0; j < 4; j++)
                Ss[str + i][stc + j] = sacc[i][j];
        __syncthreads();

        #pragma unroll
        for (int i = 0; i < 6; i++) {
            int f = t + i * 128;
            int r = f / 12, c = (f % 12) * 4;
            int gk = kbase + r;
            float4 v = make_float4(0.f, 0.f, 0.f, 0.f);
            if (gk < T)
                v = *reinterpret_cast<const float4*>(d_v + ((size_t)b * T + gk) * C + h * HD + c);
            *reinterpret_cast<float4*>(&KVs[r][c]) = v;
        }

        {
            float mloc = -INFINITY;
            for (int j = sub; j < nk; j += 2) mloc = fmaxf(mloc, Ss[rA][j]);
            mloc = fmaxf(mloc, __shfl_xor_sync(0xffffffffu, mloc, 1));
            float mold = mrow[rA];
            float mnew = fmaxf(mold, mloc);
            float ls = 0.f;
            for (int j = sub; j < nk; j += 2) {
                float p = __expf(Ss[rA][j] - mnew);
                Ss[rA][j] = p;
                ls += p;
            }
            ls += __shfl_xor_sync(0xffffffffu, ls, 1);
            if (sub == 0) {
                float al = __expf(mold - mnew);
                mrow[rA] = mnew;
                lrow[rA] = lrow[rA] * al + ls;
                alpha_s[rA] = al;
            }
        }
        __syncthreads();

        float a0 = alpha_s[rp], a1 = alpha_s[rp + 32];
        #pragma unroll
        for (int c = 0; c < 12; c++) { o0[c] *= a0; o1[c] *= a1; }
        for (int j = 0; j < nk; j++) {
            float p0 = Ss[rp][j], p1 = Ss[rp + 32][j];
            float4 v0 = *reinterpret_cast<const float4*>(&KVs[j][cg]);
            float4 v1 = *reinterpret_cast<const float4*>(&KVs[j][cg + 4]);
            float4 v2 = *reinterpret_cast<const float4*>(&KVs[j][cg + 8]);
            float vv[12] = {v0.x, v0.y, v0.z, v0.w, v1.x, v1.y, v1.z, v1.w,
                            v2.x, v2.y, v2.z, v2.w};
            #pragma unroll
            for (int c = 0; c < 12; c++) {
                o0[c] = fmaf(p0, vv[c], o0[c]);
                o1[c] = fmaf(p1, vv[c], o1[c]);
            }
        }
        __syncthreads();
    }

    int gq0 = q0 + rp, gq1 = q0 + rp + 32;
    if (gq0 < T) {
        float inv = 1.f / lrow[rp];
        float* op = d_ao + ((size_t)b * T + gq0) * C + h * HD + cg;
        #pragma unroll
        for (int c = 0; c < 12; c += 4) {
            float4 w = make_float4(o0[c] * inv, o0[c + 1] * inv, o0[c + 2] * inv, o0[c + 3] * inv);
            *reinterpret_cast<float4*>(op + c) = w;
        }
    }
    if (gq1 < T) {
        float inv = 1.f / lrow[rp + 32];
        float* op = d_ao + ((size_t)b * T + gq1) * C + h * HD + cg;
        #pragma unroll
        for (int c = 0; c < 12; c += 4) {
            float4 w = make_float4(o1[c] * inv, o1[c + 1] * inv, o1[c + 2] * inv, o1[c + 3] * inv);
            *reinterpret_cast<float4*>(op + c) = w;
        }
    }
}

// ---------------- ci / ca / rank / gather ----------------
__global__ void ci_part_kernel() {
    int b = blockIdx.x, chunk = blockIdx.y;
    int c = threadIdx.x;
    int t0 = chunk * 99, t1 = min(T, t0 + 99);
    float s = 0.f;
    for (int t = t0; t < t1; t++) s += d_mhsa[((size_t)b * T + t) * C + c];
    d_cipart[((size_t)b * 8 + chunk) * C + c] = s;
}
__global__ void ci_final_kernel() {
    int b = blockIdx.x;
    int c = threadIdx.x;
    float s = 0.f;
    #pragma unroll
    for (int k = 0; k < 8; k++) s += d_cipart[((size_t)b * 8 + k) * C + c];
    float mu = s / (float)T;
    d_ci[b * C + c] = 1.f / (1.f + expf(-mu));
}
__global__ void ca_kernel() {
    int row = blockIdx.x * 8 + (threadIdx.x >> 5);
    int lane = threadIdx.x & 31;
    if (row >= Bb * HW) return;
    int b = row / HW, n = row - b * HW;
    const float* p = d_res1 + ((size_t)b * T + 1 + n) * C;
    const float* cc = d_ci + b * C;
    float s = 0.f;
    for (int i = lane; i < C; i += 32) s = fmaf(p[i], cc[i], s);
    #pragma unroll
    for (int o = 16; o > 0; o >>= 1) s += __shfl_down_sync(0xffffffffu, s, o);
    if (lane == 0) d_ca[row] = s;
}
__global__ void rank_kernel() {
    int b = blockIdx.x;
    __shared__ float s[HW];
    for (int i = threadIdx.x; i < HW; i += blockDim.x) s[i] = d_ca[b * HW + i];
    __syncthreads();
    for (int n = threadIdx.x; n < HW; n += blockDim.x) {
        float v = s[n];
        int r = 0;
        for (int mm = 0; mm < HW; mm++) {
            float u = s[mm];
            r += (u < v) || (u == v && mm < n);
        }
        if (r >= CUT) d_sel[b * NPOOL + (r - CUT)] = n;
    }
}
__global__ void gather_kernel() {
    int idx = blockIdx.x * blockDim.x + threadIdx.x;
    if (idx >= X2N) return;
    int b = idx / (TP * C);
    int rem = idx - b * (TP * C);
    int t = rem / C;
    int c = rem - t * C;
    int srcrow = (t == 0) ? 0 : (1 + d_sel[b * NPOOL + t - 1]);
    d_x2[idx] = d_res1[((size_t)b * T + srcrow) * C + c];
}

// ---------------- launch ----------------
extern "C" void kernel_launch(void* const* d_in, const int* in_sizes, int n_in,
                              void* d_out, int out_size) {
    const float* x    = (const float*)d_in[0];
    const float* cls  = (const float*)d_in[1];
    const float* wln1 = (const float*)d_in[2];
    const float* bln1 = (const float*)d_in[3];
    const float* Wq   = (const float*)d_in[4];
    const float* Wk   = (const float*)d_in[5];
    const float* Wv   = (const float*)d_in[6];
    const float* Wo   = (const float*)d_in[7];
    const float* wln2 = (const float*)d_in[8];
    const float* bln2 = (const float*)d_in[9];
    const float* W1   = (const float*)d_in[10];
    const float* W2   = (const float*)d_in[11];
    float* out = (float*)d_out;

    float *p_xin, *p_x1, *p_q, *p_k, *p_v, *p_ao, *p_mhsa, *p_res1, *p_x2, *p_x2n, *p_h1;
    cudaGetSymbolAddress((void**)&p_xin,  d_xin);
    cudaGetSymbolAddress((void**)&p_x1,   d_x1);
    cudaGetSymbolAddress((void**)&p_q,    d_q);
    cudaGetSymbolAddress((void**)&p_k,    d_k);
    cudaGetSymbolAddress((void**)&p_v,    d_v);
    cudaGetSymbolAddress((void**)&p_ao,   d_ao);
    cudaGetSymbolAddress((void**)&p_mhsa, d_mhsa);
    cudaGetSymbolAddress((void**)&p_res1, d_res1);
    cudaGetSymbolAddress((void**)&p_x2,   d_x2);
    cudaGetSymbolAddress((void**)&p_x2n,  d_x2n);
    cudaGetSymbolAddress((void**)&p_h1,   d_h1);

    __nv_bfloat16 *b_x2n, *b_w1, *b_h1, *b_w2;
    cudaGetSymbolAddress((void**)&b_x2n,  s_x2n);
    cudaGetSymbolAddress((void**)&b_w1,   s_w1);
    cudaGetSymbolAddress((void**)&b_h1,   s_h1);
    cudaGetSymbolAddress((void**)&b_w2,   s_w2);

    auto blk = [](int n) { return (n + 255) / 256; };

    concat_ln_kernel<<<Bb, 1024>>>(x, cls, wln1, bln1);

    // ---- ranking path: fp32 SIMT GEMMs (proven at rel_err 8.7e-7) ----
    int Mqkv = MTOK;
    dim3 gqkv(C / 128, (Mqkv + 127) / 128);
    gemm_nt<0><<<gqkv, 256>>>(p_x1, Wq, p_q, Mqkv, C, C, nullptr, nullptr);
    gemm_nt<0><<<gqkv, 256>>>(p_x1, Wk, p_k, Mqkv, C, C, nullptr, nullptr);
    gemm_nt<0><<<gqkv, 256>>>(p_x1, Wv, p_v, Mqkv, C, C, nullptr, nullptr);

    attn_kernel<<<dim3((T + 63) / 64, NH, Bb), 128>>>();

    gemm_nt<2><<<gqkv, 256>>>(p_ao, Wo, p_mhsa, Mqkv, C, C, p_xin, p_res1);

    ci_part_kernel<<<dim3(Bb, 8), C>>>();
    ci_final_kernel<<<Bb, C>>>();
    ca_kernel<<<(Bb * HW + 7) / 8, 256>>>();
    rank_kernel<<<Bb, 256>>>();
    gather_kernel<<<blk(X2N), 256>>>();

    ln_kernel<<<Bb, 1024>>>(p_x2, wln2, bln2, p_x2n, TP);

    // ---- FFN path: tensor cores, asymmetric 3-term splits ----
    split_wt_kernel<<<blk(FF * C), 256>>>(W1, b_w1, FF, C);
    split_wt_kernel<<<blk(C * FF), 256>>>(W2, b_w2, C, FF);
    split_act_kernel<<<blk(MP * C), 256>>>(p_x2n, b_x2n, MP, C);
    gemm_mma<1><<<dim3(FF / 128, (MP + 127) / 128), 256>>>(
        b_x2n, b_w1, p_h1, MP, FF, 3 * C, nullptr, nullptr);

    split_act_kernel<<<blk(MP * FF), 256>>>(p_h1, b_h1, MP, FF);
    gemm_mma<3><<<dim3(C / 128, (MP + 127) / 128), 256>>>(
        b_h1, b_w2, nullptr, MP, C, 3 * FF, p_x2n, out);
}